// round 15
// baseline (speedup 1.0000x reference)
#include <cuda_runtime.h>
#include <cuda_bf16.h>
#include <cstdint>

#define B_    16
#define N_    256
#define DIN_  64
#define DOUT_ 64
#define K_    128
#define WSTR  72      // split-row stride (floats): halves at +0 and +36
#define DHOF  36      // second d-half offset (floats); 144 B = 16B-aligned, disjoint banks

typedef unsigned long long u64t;

// Scratch (allocation-free: __device__ globals)
__device__ float g_logits[B_ * N_ * N_];   // 4 MB, L2-resident
__device__ float g_h[B_ * N_ * DOUT_];
__device__ float g_scores[B_ * N_];

// pair index -> (ti, tj) LUT for 8x8 upper triangle (36 pairs)
__constant__ unsigned char c_ti[36] = {
    0,0,0,0,0,0,0,0, 1,1,1,1,1,1,1, 2,2,2,2,2,2,
    3,3,3,3,3, 4,4,4,4, 5,5,5, 6,6, 7};
__constant__ unsigned char c_tj[36] = {
    0,1,2,3,4,5,6,7, 1,2,3,4,5,6,7, 2,3,4,5,6,7,
    3,4,5,6,7, 4,5,6,7, 5,6,7, 6,7, 7};

// packed fp32x2 ops (Blackwell; ptxas never auto-fuses these)
__device__ __forceinline__ u64t ffma2(u64t a, u64t b, u64t c) {
    u64t d;
    asm("fma.rn.f32x2 %0, %1, %2, %3;" : "=l"(d) : "l"(a), "l"(b), "l"(c));
    return d;
}
__device__ __forceinline__ u64t fmul2(u64t a, u64t b) {
    u64t d;
    asm("mul.rn.f32x2 %0, %1, %2;" : "=l"(d) : "l"(a), "l"(b));
    return d;
}
__device__ __forceinline__ u64t fadd2(u64t a, u64t b) {
    u64t d;
    asm("add.rn.f32x2 %0, %1, %2;" : "=l"(d) : "l"(a), "l"(b));
    return d;
}
__device__ __forceinline__ float u64lo(u64t v) { return __uint_as_float((unsigned)v); }
__device__ __forceinline__ float u64hi(u64t v) { return __uint_as_float((unsigned)(v >> 32)); }

// fast tanh: 2 MUFU + few ALU, rel err ~1e-6, off the fma pipe
__device__ __forceinline__ float tanh_fast(float v) {
    float av = fabsf(v);
    float t  = __expf(-2.0f * av);
    float r  = __fdividef(1.0f - t, 1.0f + t);
    return copysignf(r, v);
}

// ============================================================================
// Kernel 1: symmetric logits, d-split across lane halves.
// Grid (36 tile-pairs, B). Block 256 = 8 warps, 2 CTAs/SM.
// lane = jh (0..15) | dh<<4 ; warp w: jbase=(w&1)*16, igrp=w>>2... (w>>1).
// 4 passes x (2 rows/warp): each thread holds pr for 2 rows x its 32 d's.
// Per e: 8 LDS.128 (wt half) + 32 FFMA2 + shfl.xor(16) combine + 1 tanh.
// ============================================================================
__global__ void __launch_bounds__(256, 2)
logits_kernel(const float* __restrict__ x,
              const float* __restrict__ W_att, const float* __restrict__ b_att,
              const float* __restrict__ att_w)
{
    __shared__ __align__(16) float xi_s[32 * WSTR];
    __shared__ __align__(16) float xj_s[32 * WSTR];
    __shared__ __align__(16) float wt[64 * WSTR];   // wt[e][d] split halves
    __shared__ float batt[64], aw[64];
    __shared__ float st[32 * 33];                   // mirror transpose staging

    const int b   = blockIdx.y;
    const int tid = threadIdx.x;

    const int ti  = c_ti[blockIdx.x];
    const int tj  = c_tj[blockIdx.x];
    const int gi0 = ti * 32, gj0 = tj * 32;

    // ---- cooperative loads (split-half layout: d<32 at +0, d>=32 at +DHOF) ----
    {
        const float4* xa = (const float4*)(x + ((size_t)b * N_ + gi0) * DIN_);
        const float4* xb = (const float4*)(x + ((size_t)b * N_ + gj0) * DIN_);
        #pragma unroll
        for (int t = tid; t < 512; t += 256) {
            int r = t >> 4, c = t & 15;                       // c = float4 index (d=4c)
            int off = r * WSTR + ((c < 8) ? 4 * c : DHOF + 4 * (c - 8));
            *(float4*)(xi_s + off) = xa[t];
            *(float4*)(xj_s + off) = xb[t];
        }
    }
    #pragma unroll
    for (int t = tid; t < 4096; t += 256) {
        int d = t >> 6, e = t & 63;
        wt[e * WSTR + ((d < 32) ? d : DHOF + d - 32)] = W_att[t];
    }
    if (tid < 64) { batt[tid] = b_att[tid]; aw[tid] = att_w[tid]; }
    __syncthreads();

    const int lane = tid & 31;
    const int w    = tid >> 5;
    const int jh   = lane & 15;
    const int dh   = lane >> 4;
    const int jl   = (w & 1) * 16 + jh;      // j within tile
    const int igrp = w >> 1;                 // 0..3

    // xj half in registers, fixed for whole kernel: 32 floats = 16 u64
    u64t xjr[16];
    {
        const ulonglong2* xp = (const ulonglong2*)(xj_s + jl * WSTR + dh * DHOF);
        #pragma unroll
        for (int c = 0; c < 8; c++) {
            ulonglong2 v = xp[c];
            xjr[2*c] = v.x; xjr[2*c + 1] = v.y;
        }
    }

    #pragma unroll 1
    for (int p = 0; p < 4; p++) {
        const int rowa = igrp * 2 + 8 * p;   // rows {rowa, rowa+1}
        // build pr for both rows (xi broadcast within dh-group)
        u64t pr0[16], pr1[16];
        {
            const ulonglong2* xa = (const ulonglong2*)(xi_s + rowa * WSTR + dh * DHOF);
            const ulonglong2* xb = (const ulonglong2*)(xi_s + (rowa + 1) * WSTR + dh * DHOF);
            #pragma unroll
            for (int c = 0; c < 8; c++) {
                ulonglong2 va = xa[c];
                ulonglong2 vb = xb[c];
                pr0[2*c]     = fmul2(va.x, xjr[2*c]);
                pr0[2*c + 1] = fmul2(va.y, xjr[2*c + 1]);
                pr1[2*c]     = fmul2(vb.x, xjr[2*c]);
                pr1[2*c + 1] = fmul2(vb.y, xjr[2*c + 1]);
            }
        }

        float lg = 0.0f;
        #pragma unroll 1
        for (int e = 0; e < 64; e++) {
            const ulonglong2* wrp = (const ulonglong2*)(wt + e * WSTR + dh * DHOF);
            u64t a0 = 0ull, a1 = 0ull, b0 = 0ull, b1 = 0ull;
            #pragma unroll
            for (int c = 0; c < 8; c++) {
                ulonglong2 wv = wrp[c];                 // broadcast per dh-group
                a0 = ffma2(pr0[2*c],     wv.x, a0);
                a1 = ffma2(pr0[2*c + 1], wv.y, a1);
                b0 = ffma2(pr1[2*c],     wv.x, b0);
                b1 = ffma2(pr1[2*c + 1], wv.y, b1);
            }
            u64t sa = fadd2(a0, a1);
            u64t sb = fadd2(b0, b1);
            float va = u64lo(sa) + u64hi(sa);
            float vb = u64lo(sb) + u64hi(sb);
            va += __shfl_xor_sync(~0u, va, 16);         // combine d-halves
            vb += __shfl_xor_sync(~0u, vb, 16);
            float v = (dh ? vb : va) + batt[e];         // own row: rowa+dh
            lg = fmaf(tanh_fast(v), aw[e], lg);
        }
        lg *= 0.5f;   // / TEMP

        const int own = rowa + dh;
        g_logits[((size_t)b * N_ + gi0 + own) * N_ + gj0 + jl] = lg;
        st[own * 33 + jl] = lg;
    }

    if (ti != tj) {
        __syncthreads();
        #pragma unroll
        for (int t = tid; t < 1024; t += 256) {
            int r = t >> 5, c = t & 31;
            g_logits[((size_t)b * N_ + gj0 + r) * N_ + gi0 + c] = st[c * 33 + r];
        }
    }
}

// ============================================================================
// Kernel 2: warp-per-row epilogue with x_b staged in smem (kills redundant
// 64KB/warp L2 streams). Grid (32, B), block 256 = 8 warps.
// ============================================================================
#define EP_SMEM (16384 * 4 + 8 * 256 * 4 + 8 * 64 * 4)   // x(64KB) + A + agg = 75776 B

__global__ void __launch_bounds__(256, 1)
epilogue_kernel(const float* __restrict__ x,
                const float* __restrict__ W_pwa, const float* __restrict__ b_pwa,
                const float* __restrict__ W_pna, const float* __restrict__ b_pna,
                const float* __restrict__ bn_scale, const float* __restrict__ bn_bias,
                const float* __restrict__ pool_w, const float* __restrict__ pool_b)
{
    extern __shared__ __align__(16) float esm[];
    float* xs     = esm;                 // 256 x 64
    float* A_all  = esm + 16384;         // 8 x 256
    float* agg_all= A_all + 2048;        // 8 x 64

    const int b    = blockIdx.y;
    const int warp = threadIdx.x >> 5;
    const int lane = threadIdx.x & 31;
    const int i    = blockIdx.x * 8 + warp;

    // stage x_b
    {
        const float4* xb4 = (const float4*)(x + (size_t)b * N_ * DIN_);
        #pragma unroll
        for (int t = threadIdx.x; t < 4096; t += 256)
            ((float4*)xs)[t] = xb4[t];
    }
    __syncthreads();

    float* A_sm   = A_all + warp * 256;
    float* agg_sm = agg_all + warp * 64;

    // softmax over row i (8 logits per lane, stride 32: coalesced)
    const float* lrow = g_logits + ((size_t)b * N_ + i) * N_;
    float lg[8];
    #pragma unroll
    for (int k = 0; k < 8; k++) lg[k] = lrow[lane + 32 * k];
    float mx = lg[0];
    #pragma unroll
    for (int k = 1; k < 8; k++) mx = fmaxf(mx, lg[k]);
    #pragma unroll
    for (int o = 16; o; o >>= 1) mx = fmaxf(mx, __shfl_xor_sync(~0u, mx, o));
    float wv[8], sum = 0.f;
    #pragma unroll
    for (int k = 0; k < 8; k++) { wv[k] = __expf(lg[k] - mx); sum += wv[k]; }
    #pragma unroll
    for (int o = 16; o; o >>= 1) sum += __shfl_xor_sync(~0u, sum, o);
    float inv = 1.0f / sum;
    #pragma unroll
    for (int k = 0; k < 8; k++) A_sm[lane + 32 * k] = wv[k] * inv;
    __syncwarp();

    // agg[d] for d = 2*lane, 2*lane+1 (all reads from smem)
    float s0 = 0.f, s1 = 0.f;
    #pragma unroll 4
    for (int j = 0; j < N_; j++) {
        float2 xv = *(const float2*)(xs + j * DIN_ + 2 * lane);
        float aj = A_sm[j];
        s0 = fmaf(aj, xv.x, s0);
        s1 = fmaf(aj, xv.y, s1);
    }
    agg_sm[2 * lane]     = s0;
    agg_sm[2 * lane + 1] = s1;
    __syncwarp();

    // h for e = 2*lane, 2*lane+1
    const int e0 = 2 * lane;
    float2 bpw = *(const float2*)(b_pwa + e0);
    float2 bpn = *(const float2*)(b_pna + e0);
    float h0 = bpw.x + bpn.x, h1 = bpw.y + bpn.y;
    const float* xi = xs + i * DIN_;
    #pragma unroll 4
    for (int d = 0; d < DIN_; d++) {
        float2 wp = *(const float2*)(W_pwa + d * 64 + e0);
        float2 wn = *(const float2*)(W_pna + d * 64 + e0);
        float ad = agg_sm[d];
        float xd = xi[d];
        h0 = fmaf(ad, wp.x, h0); h1 = fmaf(ad, wp.y, h1);
        h0 = fmaf(xd, wn.x, h0); h1 = fmaf(xd, wn.y, h1);
    }
    float2 bs = *(const float2*)(bn_scale + e0);
    float2 bz = *(const float2*)(bn_bias + e0);
    const float inv_std = rsqrtf(1.0f + 1e-5f);
    h0 = fmaf(h0, bs.x * inv_std, bz.x);
    h1 = fmaf(h1, bs.y * inv_std, bz.y);
    const float SC = 1.0507009873554805f;
    const float AL = 1.6732632423543772f;
    h0 = (h0 > 0.f) ? SC * h0 : SC * AL * expm1f(h0);
    h1 = (h1 > 0.f) ? SC * h1 : SC * AL * expm1f(h1);
    *(float2*)(g_h + ((size_t)b * N_ + i) * DOUT_ + e0) = make_float2(h0, h1);

    float2 pw = *(const float2*)(pool_w + e0);
    float v = h0 * pw.x + h1 * pw.y;
    #pragma unroll
    for (int o = 16; o; o >>= 1) v += __shfl_xor_sync(~0u, v, o);
    if (lane == 0)
        g_scores[b * N_ + i] = 1.0f / (1.0f + __expf(-(v + pool_b[0])));
}

// ============================================================================
// Kernel 3: sync-free exact top-k by rank counting + coalesced gather
// (key = score bits desc, index asc tiebreak -> matches lax.top_k ordering)
// ============================================================================
__global__ void __launch_bounds__(256)
topk_kernel(float* __restrict__ out)
{
    __shared__ unsigned long long keys[N_];
    __shared__ int   inv[K_];
    __shared__ float ssc[K_];
    const int b = blockIdx.x, tid = threadIdx.x;

    float sc = g_scores[b * N_ + tid];
    unsigned long long mykey =
        ((unsigned long long)__float_as_uint(sc) << 32)
        | (unsigned)(0xFFFFFFFFu - (unsigned)tid);
    keys[tid] = mykey;
    __syncthreads();

    int rank = 0;
    #pragma unroll 8
    for (int j = 0; j < N_; j++) rank += (keys[j] > mykey);   // broadcast LDS
    if (rank < K_) { inv[rank] = tid; ssc[rank] = sc; }
    __syncthreads();

    #pragma unroll
    for (int t = tid; t < K_ * DOUT_; t += N_) {
        int r = t >> 6, e = t & 63;
        out[((size_t)b * K_ + r) * DOUT_ + e] =
            g_h[((size_t)b * N_ + inv[r]) * DOUT_ + e] * ssc[r];
    }
}

extern "C" void kernel_launch(void* const* d_in, const int* in_sizes, int n_in,
                              void* d_out, int out_size)
{
    const float* x        = (const float*)d_in[0];
    const float* W_att    = (const float*)d_in[1];
    const float* b_att    = (const float*)d_in[2];
    const float* att_w    = (const float*)d_in[3];
    const float* W_pwa    = (const float*)d_in[4];
    const float* b_pwa    = (const float*)d_in[5];
    const float* W_pna    = (const float*)d_in[6];
    const float* b_pna    = (const float*)d_in[7];
    const float* bn_scale = (const float*)d_in[8];
    const float* bn_bias  = (const float*)d_in[9];
    const float* pool_w   = (const float*)d_in[10];
    const float* pool_b   = (const float*)d_in[11];
    float* out = (float*)d_out;

    cudaFuncSetAttribute(epilogue_kernel,
                         cudaFuncAttributeMaxDynamicSharedMemorySize, EP_SMEM);

    logits_kernel<<<dim3(36, B_), 256>>>(x, W_att, b_att, att_w);
    epilogue_kernel<<<dim3(32, B_), 256, EP_SMEM>>>(x, W_pwa, b_pwa, W_pna, b_pna,
                                                    bn_scale, bn_bias, pool_w, pool_b);
    topk_kernel<<<B_, 256>>>(out);
}